// round 2
// baseline (speedup 1.0000x reference)
#include <cuda_runtime.h>

// LS_loss: fused channel-statistics reduction + closed-form loss finalize.
//
// Shapes: input, img_mean : (32, 4, 512, 512) fp32, row-major contiguous.
// 128 channels of 262144 contiguous floats each (= 65536 float4).
//
// Math (per channel, N = 262144):
//   Hea = 0.5*(1+tanh(x/0.05))
//   A = sum(Hea), B1 = sum(Hea*img), S = sum(img), Q = sum(img^2)
//   c1 = B1/(A+eps), c2 = (S-B1)/(N-A+eps)
//   chan = Q - 2*(c1*B1 + c2*(S-B1)) + c1^2*A + c2^2*(N-A)
//   out  = sum(chan) / (B*C*H*W)

#define N_PER_CH   262144          // 512*512
#define F4_PER_CH  65536           // N_PER_CH / 4
#define BLKS_PER_CH 16
#define NBLOCKS    (128 * BLKS_PER_CH)   // 2048
#define F4_PER_BLK (F4_PER_CH / BLKS_PER_CH) // 4096
#define THREADS    256
#define F4_PER_THR (F4_PER_BLK / THREADS)    // 16
#define LS_EPS     1e-4f
#define INV_EPISON 20.0f

// Scratch for block partials: 2048 * float4 = 32 KB. Static device global
// (allocation-free per harness rules).
static __device__ float4 g_partials[NBLOCKS];

__device__ __forceinline__ float tanh_fast(float x) {
    float y;
    asm("tanh.approx.f32 %0, %1;" : "=f"(y) : "f"(x));
    return y;
}

__device__ __forceinline__ void accum1(float x, float m,
                                       float& sH, float& sHI, float& sI, float& sI2) {
    float h = fmaf(0.5f, tanh_fast(INV_EPISON * x), 0.5f);
    sH  += h;
    sHI  = fmaf(h, m, sHI);
    sI  += m;
    sI2  = fmaf(m, m, sI2);
}

__global__ void __launch_bounds__(THREADS)
ls_loss_pass1(const float4* __restrict__ inp, const float4* __restrict__ img)
{
    const int b = blockIdx.x;
    const int t = threadIdx.x;
    // Block b covers float4 range [b*4096, (b+1)*4096) — entirely inside one
    // channel since 16 blocks per channel tile it exactly.
    const long base = (long)b * F4_PER_BLK;

    float sH = 0.f, sHI = 0.f, sI = 0.f, sI2 = 0.f;

    #pragma unroll
    for (int i = 0; i < F4_PER_THR; i++) {
        const long idx = base + (long)i * THREADS + t;
        float4 x = inp[idx];
        float4 m = img[idx];
        accum1(x.x, m.x, sH, sHI, sI, sI2);
        accum1(x.y, m.y, sH, sHI, sI, sI2);
        accum1(x.z, m.z, sH, sHI, sI, sI2);
        accum1(x.w, m.w, sH, sHI, sI, sI2);
    }

    // Warp reduce (deterministic tree)
    #pragma unroll
    for (int o = 16; o > 0; o >>= 1) {
        sH  += __shfl_down_sync(0xFFFFFFFFu, sH,  o);
        sHI += __shfl_down_sync(0xFFFFFFFFu, sHI, o);
        sI  += __shfl_down_sync(0xFFFFFFFFu, sI,  o);
        sI2 += __shfl_down_sync(0xFFFFFFFFu, sI2, o);
    }

    __shared__ float4 sm[THREADS / 32];
    const int warp = t >> 5, lane = t & 31;
    if (lane == 0) sm[warp] = make_float4(sH, sHI, sI, sI2);
    __syncthreads();

    if (t == 0) {
        float4 tot = sm[0];
        #pragma unroll
        for (int w = 1; w < THREADS / 32; w++) {
            float4 v = sm[w];
            tot.x += v.x; tot.y += v.y; tot.z += v.z; tot.w += v.w;
        }
        g_partials[b] = tot;
    }
}

__global__ void __launch_bounds__(128)
ls_loss_pass2(float* __restrict__ out)
{
    const int c = threadIdx.x;   // one channel per thread, 128 channels

    float A = 0.f, B1 = 0.f, S = 0.f, Q = 0.f;
    #pragma unroll
    for (int i = 0; i < BLKS_PER_CH; i++) {
        float4 v = g_partials[c * BLKS_PER_CH + i];
        A += v.x; B1 += v.y; S += v.z; Q += v.w;
    }

    const float N  = (float)N_PER_CH;
    const float s3 = N - A;
    const float c1 = B1 / (A + LS_EPS);
    const float c2 = (S - B1) / (s3 + LS_EPS);

    float chan = Q - 2.f * (c1 * B1 + c2 * (S - B1))
               + c1 * c1 * A + c2 * c2 * s3;

    // Reduce 128 values (4 warps)
    #pragma unroll
    for (int o = 16; o > 0; o >>= 1)
        chan += __shfl_down_sync(0xFFFFFFFFu, chan, o);

    __shared__ float sm[4];
    if ((c & 31) == 0) sm[c >> 5] = chan;
    __syncthreads();

    if (c == 0) {
        float tot = sm[0] + sm[1] + sm[2] + sm[3];
        out[0] = tot / (float)(32 * 4 * N_PER_CH);
    }
}

extern "C" void kernel_launch(void* const* d_in, const int* in_sizes, int n_in,
                              void* d_out, int out_size)
{
    const float4* inp = (const float4*)d_in[0];   // 'input'
    const float4* img = (const float4*)d_in[1];   // 'img_mean'
    float* out = (float*)d_out;

    ls_loss_pass1<<<NBLOCKS, THREADS>>>(inp, img);
    ls_loss_pass2<<<1, 128>>>(out);
}